// round 14
// baseline (speedup 1.0000x reference)
#include <cuda_runtime.h>

#define N_AGENTS 4096
#define TPB 256
#define JPT 16          // 4096/256 candidates per thread
#define TOPK 32

// ---- static smem layout (byte offsets), phase-disjoint aliases ----
#define OFF_W2S   0        // f32[128*64] 32768B, XOR-swizzled rows (conv2)
                           //   alias: sorted keys u32[16][256] 16384B (selection)
#define OFF_Z1    0        //   alias: f32[64]  (post-conv2)
#define OFF_Z2    256      //   alias: f32[128]
#define OFF_Z3    768      //   alias: f32[64]
#define OFF_Z4    1024     //   alias: f32[4]
#define OFF_H1S   32768    // f32[64*32] 8192B (conv phases)
#define OFF_SKEY  32768    //   alias: u32[256] 1024B (merge, pre-conv1)
#define OFF_W1S   40960    // f32[320] 1280B
#define OFF_B1S   42240    // f32[64]  256B
#define OFF_B2S   42496    // f32[128] 512B
#define OFF_XK    43008    // f32[160] 640B  (alias: featsh[0..127] post-conv1)
#define OFF_MASK  43648    // f32[32]  128B
#define OFF_SEL   43776    // u32[32]  128B
#define OFF_TAIL  43904    // f32[4]   16B   (rel.x, rel.y, v2, v3)
#define SMEM_TOTAL 43920

#define KEY_BIAS 0x3C000000u

__global__ __launch_bounds__(TPB, 5)
void controller_kernel(
    const float4* __restrict__ states4,   // [N,4]
    const float*  __restrict__ goals,     // [N,2]
    const float*  __restrict__ W1,  const float* __restrict__ b1,
    const float*  __restrict__ W2,  const float* __restrict__ b2,
    const float*  __restrict__ Wd1, const float* __restrict__ bd1,
    const float*  __restrict__ Wd2, const float* __restrict__ bd2,
    const float*  __restrict__ Wd3, const float* __restrict__ bd3,
    const float*  __restrict__ Wd4, const float* __restrict__ bd4,
    float* __restrict__ out)              // [N,2]
{
    __shared__ __align__(16) char smem[SMEM_TOTAL];
    float4*             w2s4    = (float4*)(smem + OFF_W2S);
    unsigned*           sortbuf = (unsigned*)(smem + OFF_W2S);    // alias (selection)
    float*              h1s     = (float*)(smem + OFF_H1S);
    unsigned*           skey32  = (unsigned*)(smem + OFF_SKEY);
    float*              W1s     = (float*)(smem + OFF_W1S);
    float*              b1s     = (float*)(smem + OFF_B1S);
    float*              b2s     = (float*)(smem + OFF_B2S);
    float*              xkflat  = (float*)(smem + OFF_XK);
    float*              featsh  = (float*)(smem + OFF_XK);        // alias (post-conv1)
    float*              masksh  = (float*)(smem + OFF_MASK);
    unsigned*           selsh   = (unsigned*)(smem + OFF_SEL);
    float*              tailf   = (float*)(smem + OFF_TAIL);
    float*              z1s     = (float*)(smem + OFF_Z1);
    float*              z2s     = (float*)(smem + OFF_Z2);
    float*              z3s     = (float*)(smem + OFF_Z3);
    float*              z4s     = (float*)(smem + OFF_Z4);

    const int tid  = threadIdx.x;
    const int i    = blockIdx.x;
    const int lane = tid & 31;
    const int wid  = tid >> 5;

    const float4 si = states4[i];

    // ---- phase A: planar distances -> exact u32 keys (monotone in (d, k)) ----
    unsigned key[JPT];
    {
        const float2* stxy = (const float2*)states4;
        #pragma unroll
        for (int k = 0; k < JPT; k++) {
            int j = tid + (k << 8);
            float2 sj = stxy[2 * j];
            float dx = si.x - sj.x;
            float dy = si.y - sj.y;
            float d  = sqrtf(dx * dx + dy * dy + 1e-4f);   // identical to ref path
            key[k] = ((__float_as_uint(d) - KEY_BIAS) << 4) | (unsigned)k;
        }
    }

    // ---- per-thread Batcher odd-even mergesort of 16 keys (registers, 63 CEs) ----
    #pragma unroll
    for (int p = 1; p < 16; p <<= 1) {
        #pragma unroll
        for (int q = p; q > 0; q >>= 1) {
            #pragma unroll
            for (int jj = (q & (p - 1)); jj + q < 16; jj += (q << 1)) {
                #pragma unroll
                for (int ii = 0; ii < q; ii++) {
                    if (ii + jj + q < 16 &&
                        ((ii + jj) / (p << 1) == (ii + jj + q) / (p << 1))) {
                        unsigned a = key[ii + jj], b = key[ii + jj + q];
                        key[ii + jj]     = umin(a, b);
                        key[ii + jj + q] = umax(a, b);
                    }
                }
            }
        }
    }
    // spill sorted column to smem (own column only -> warp-sync safe, no barrier)
    #pragma unroll
    for (int k = 0; k < 16; k++) sortbuf[(k << 8) + tid] = key[k];

    // ---- stage 1: per-warp exact top-32, REDUX tournament ----
    unsigned winkey = 0;
    int      winlane = 0;
    {
        unsigned cur = key[0];
        int head = 1;
        #pragma unroll
        for (int r = 0; r < TOPK; r++) {
            unsigned g = __reduce_min_sync(0xffffffffu, cur);
            unsigned mm = __ballot_sync(0xffffffffu, cur == g);
            int l = __ffs(mm) - 1;          // lowest lane = lowest j on key ties
            if (lane == r) { winkey = g; winlane = l; }
            if (lane == l) {                // winner pops next from its sorted list
                cur = (head < 16) ? sortbuf[(head << 8) + tid] : 0xffffffffu;
                head++;
            }
        }
    }
    // publish rank-`lane` winner: u32 key to smem, its j kept in a register
    const unsigned myj = (unsigned)((wid << 5) + winlane) + ((winkey & 15u) << 8);
    skey32[tid] = winkey;
    __syncthreads();

    // ---- merge phase: stage weights (overlaps LDS chains) + rank-merge ----
    for (int t = tid; t < 320; t += TPB) W1s[t] = W1[t];
    if (tid < 64)  b1s[tid] = b1[tid];
    if (tid < 128) b2s[tid] = b2[tid];
    {
        const float4* W2v = (const float4*)W2;     // [128][16] float4
        #pragma unroll
        for (int t = tid; t < 2048; t += TPB) {
            int o = t >> 4, cb = t & 15;
            // XOR swizzle: slot = cb ^ (to & 7), to = o >> 2  -> conflict-free reads, 0B pad
            w2s4[(o << 4) + (cb ^ ((o >> 2) & 7))] = W2v[t];
        }
    }
    {
        // stable rank-merge on u32 keys: for equal keys, lower warp = lower j wins,
        // implemented exactly via <= against lower-indexed warps, < against higher.
        const unsigned mykey = winkey;
        int rank = lane;                           // position in own sorted list
        #pragma unroll
        for (int ww = 0; ww < 8; ww++) {
            if (ww == wid) continue;
            const unsigned* arr = skey32 + (ww << 5);
            const bool low = (ww < wid);
            int pos = 0;
            #pragma unroll
            for (int s = 16; s; s >>= 1) {
                unsigned v = arr[pos + s - 1];
                bool adv = low ? (v <= mykey) : (v < mykey);
                pos += adv ? s : 0;
            }
            rank += pos;
        }
        if (rank < TOPK) selsh[rank] = myj;
    }
    __syncthreads();

    // ---- gather xk rows + obs mask + tail features ----
    if (tid < TOPK) {
        int j = (int)selsh[tid];
        float4 sj = states4[j];
        float dx = si.x - sj.x;
        float dy = si.y - sj.y;
        xkflat[tid * 5 + 0] = dx;
        xkflat[tid * 5 + 1] = dy;
        xkflat[tid * 5 + 2] = si.z - sj.z;
        xkflat[tid * 5 + 3] = si.w - sj.w;
        xkflat[tid * 5 + 4] = (j == i) ? 1.0f : 0.0f;
        masksh[tid] = (sqrtf(dx * dx + dy * dy) < 1.0f) ? 1.0f : 0.0f;
    }
    if (tid == 0) {
        float gx = goals[2 * i], gy = goals[2 * i + 1];
        tailf[0] = si.x - gx;
        tailf[1] = si.y - gy;
        tailf[2] = si.z;
        tailf[3] = si.w;
    }
    __syncthreads();

    // ---- conv1 5->64, float4-vectorized (h[c][p] = xkflat[c*32+p]) ----
    {
        const float4* xk4 = (const float4*)xkflat;
        float4*       h4  = (float4*)h1s;
        #pragma unroll
        for (int u = 0; u < 2; u++) {
            int idx = tid + (u << 8);        // 0..511 float4-units
            int o = idx >> 3, p4 = idx & 7;
            float bb = b1s[o];
            float4 a = make_float4(bb, bb, bb, bb);
            #pragma unroll
            for (int c = 0; c < 5; c++) {    // c ascending: bit-identical chain
                float w = W1s[o * 5 + c];
                float4 x = xk4[(c << 3) + p4];
                a.x = fmaf(w, x.x, a.x); a.y = fmaf(w, x.y, a.y);
                a.z = fmaf(w, x.z, a.z); a.w = fmaf(w, x.w, a.w);
            }
            a.x = fmaxf(a.x, 0.0f); a.y = fmaxf(a.y, 0.0f);
            a.z = fmaxf(a.z, 0.0f); a.w = fmaxf(a.w, 0.0f);
            h4[idx] = a;
        }
    }
    __syncthreads();

    // ---- conv2 64->128 + masked argmax: f32x2 over p-pairs, 4-c blocks ----
    {
        const int to = tid >> 3;           // o base = to*4   (0..31)
        const int tp = (tid & 7) << 2;     // p base          (0..28)
        const int sw = to & 7;             // XOR-swizzle slot key for this thread
        unsigned long long accp[4][2];     // [oo][p-pair], f32x2 accumulators
        #pragma unroll
        for (int oo = 0; oo < 4; oo++) { accp[oo][0] = 0ull; accp[oo][1] = 0ull; }

        #pragma unroll 2
        for (int cb = 0; cb < 16; cb++) {
            float4 wv[4];                  // wv[oo] = W2[o, 4cb..4cb+3]
            #pragma unroll
            for (int oo = 0; oo < 4; oo++)
                wv[oo] = w2s4[(((to << 2) + oo) << 4) + (cb ^ sw)];
            #pragma unroll
            for (int cc = 0; cc < 4; cc++) {       // c ascending: bit-identical order
                const ulonglong2 hv = *reinterpret_cast<const ulonglong2*>(
                    &h1s[(((cb << 2) + cc) << 5) + tp]);
                #pragma unroll
                for (int oo = 0; oo < 4; oo++) {
                    float wsc = (cc == 0) ? wv[oo].x : (cc == 1) ? wv[oo].y
                              : (cc == 2) ? wv[oo].z : wv[oo].w;
                    unsigned long long wd;
                    asm("mov.b64 %0, {%1, %1};" : "=l"(wd) : "f"(wsc));
                    asm("fma.rn.f32x2 %0, %1, %2, %0;" : "+l"(accp[oo][0]) : "l"(wd), "l"(hv.x));
                    asm("fma.rn.f32x2 %0, %1, %2, %0;" : "+l"(accp[oo][1]) : "l"(wd), "l"(hv.y));
                }
            }
        }

        float acc[4][4];
        #pragma unroll
        for (int oo = 0; oo < 4; oo++) {
            asm("mov.b64 {%0, %1}, %2;" : "=f"(acc[oo][0]), "=f"(acc[oo][1]) : "l"(accp[oo][0]));
            asm("mov.b64 {%0, %1}, %2;" : "=f"(acc[oo][2]), "=f"(acc[oo][3]) : "l"(accp[oo][1]));
        }

        float mk[4];
        #pragma unroll
        for (int pp = 0; pp < 4; pp++) mk[pp] = masksh[tp + pp];

        #pragma unroll
        for (int oo = 0; oo < 4; oo++) {
            int o = (to << 2) + oo;
            float bb = b2s[o];
            float bv = 0.0f;
            int   bp = 0;
            #pragma unroll
            for (int pp = 0; pp < 4; pp++) {
                float v = fmaxf(acc[oo][pp] + bb, 0.0f) * mk[pp];
                if (pp == 0) { bv = v; bp = tp; }
                else if (v > bv) { bv = v; bp = tp + pp; }   // strict > keeps first index
            }
            #pragma unroll
            for (int off = 1; off < 8; off <<= 1) {
                float ov = __shfl_xor_sync(0xffffffffu, bv, off);
                int   op = __shfl_xor_sync(0xffffffffu, bp, off);
                if (ov > bv || (ov == bv && op < bp)) { bv = ov; bp = op; }
            }
            if ((tid & 7) == 0) featsh[o] = (float)bp;
        }
    }
    __syncthreads();

    // ---- MLP 132 -> 64 -> 128 -> 64 -> 4 (half-warp float4 dots) ----
    const int hw = lane >> 4;        // half-warp id (0/1)
    const int hl = lane & 15;        // lane within half

    // z1: 64 outputs, 2 per warp per iter
    #pragma unroll
    for (int it = 0; it < 4; it++) {
        int o = (wid << 3) + (it << 1) + hw;
        const float4* wr = (const float4*)(Wd1 + o * 132);
        float4 wa = wr[hl];
        float4 fa = *(const float4*)&featsh[hl << 2];
        float s = wa.x * fa.x;
        s = fmaf(wa.y, fa.y, s); s = fmaf(wa.z, fa.z, s); s = fmaf(wa.w, fa.w, s);
        float4 wb = wr[hl + 16];
        float4 fb = *(const float4*)&featsh[64 + (hl << 2)];
        s = fmaf(wb.x, fb.x, s); s = fmaf(wb.y, fb.y, s);
        s = fmaf(wb.z, fb.z, s); s = fmaf(wb.w, fb.w, s);
        if (hl == 0) {
            float4 wc = wr[32];
            float4 fc = *(const float4*)tailf;
            s = fmaf(wc.x, fc.x, s); s = fmaf(wc.y, fc.y, s);
            s = fmaf(wc.z, fc.z, s); s = fmaf(wc.w, fc.w, s);
        }
        #pragma unroll
        for (int off = 8; off; off >>= 1) s += __shfl_xor_sync(0xffffffffu, s, off);
        if (hl == 0) z1s[o] = fmaxf(s + bd1[o], 0.0f);
    }
    __syncthreads();

    // z2: 128 outputs, 2 per warp per iter
    #pragma unroll
    for (int it = 0; it < 8; it++) {
        int o = (wid << 4) + (it << 1) + hw;
        float4 w = ((const float4*)(Wd2 + (o << 6)))[hl];
        float4 z = ((const float4*)z1s)[hl];
        float s = w.x * z.x;
        s = fmaf(w.y, z.y, s); s = fmaf(w.z, z.z, s); s = fmaf(w.w, z.w, s);
        #pragma unroll
        for (int off = 8; off; off >>= 1) s += __shfl_xor_sync(0xffffffffu, s, off);
        if (hl == 0) z2s[o] = fmaxf(s + bd2[o], 0.0f);
    }
    __syncthreads();

    // z3: 64 outputs, 2 per warp per iter (128 inputs = two float4 passes)
    #pragma unroll
    for (int it = 0; it < 4; it++) {
        int o = (wid << 3) + (it << 1) + hw;
        const float4* wr = (const float4*)(Wd3 + (o << 7));
        float4 wa = wr[hl];
        float4 za = ((const float4*)z2s)[hl];
        float s = wa.x * za.x;
        s = fmaf(wa.y, za.y, s); s = fmaf(wa.z, za.z, s); s = fmaf(wa.w, za.w, s);
        float4 wb = wr[hl + 16];
        float4 zb = ((const float4*)z2s)[hl + 16];
        s = fmaf(wb.x, zb.x, s); s = fmaf(wb.y, zb.y, s);
        s = fmaf(wb.z, zb.z, s); s = fmaf(wb.w, zb.w, s);
        #pragma unroll
        for (int off = 8; off; off >>= 1) s += __shfl_xor_sync(0xffffffffu, s, off);
        if (hl == 0) z3s[o] = fmaxf(s + bd3[o], 0.0f);
    }
    __syncthreads();

    // z4: 4 outputs on warps 0-1
    if (wid < 2) {
        int o = (wid << 1) + hw;
        float4 w = ((const float4*)(Wd4 + (o << 6)))[hl];
        float4 z = ((const float4*)z3s)[hl];
        float s = w.x * z.x;
        s = fmaf(w.y, z.y, s); s = fmaf(w.z, z.z, s); s = fmaf(w.w, z.w, s);
        #pragma unroll
        for (int off = 8; off; off >>= 1) s += __shfl_xor_sync(0xffffffffu, s, off);
        if (hl == 0) z4s[o] = s + bd4[o];
    }
    __syncthreads();

    // ---- gains + control output ----
    if (tid == 0) {
        float k0 = 2.0f / (1.0f + expf(-z4s[0])) + 0.2f;
        float k1 = 2.0f / (1.0f + expf(-z4s[1])) + 0.2f;
        float k2 = 2.0f / (1.0f + expf(-z4s[2])) + 0.2f;
        float k3 = 2.0f / (1.0f + expf(-z4s[3])) + 0.2f;
        float rx = tailf[0], ry = tailf[1];
        float v2 = tailf[2], v3 = tailf[3];
        out[2 * i + 0] = -(k0 * rx + k1 * v2);
        out[2 * i + 1] = -(k2 * ry + k3 * v3);
    }
}

extern "C" void kernel_launch(void* const* d_in, const int* in_sizes, int n_in,
                              void* d_out, int out_size)
{
    (void)in_sizes; (void)n_in; (void)out_size;
    controller_kernel<<<N_AGENTS, TPB>>>(
        (const float4*)d_in[0],  (const float*)d_in[1],
        (const float*)d_in[2],   (const float*)d_in[3],
        (const float*)d_in[4],   (const float*)d_in[5],
        (const float*)d_in[6],   (const float*)d_in[7],
        (const float*)d_in[8],   (const float*)d_in[9],
        (const float*)d_in[10],  (const float*)d_in[11],
        (const float*)d_in[12],  (const float*)d_in[13],
        (float*)d_out);
}

// round 16
// speedup vs baseline: 1.0110x; 1.0110x over previous
#include <cuda_runtime.h>

#define N_AGENTS 4096
#define TPB 256
#define JPT 16          // 4096/256 candidates per thread
#define TOPK 32

// ---- static smem layout (byte offsets), phase-disjoint aliases ----
#define OFF_W2S   0        // f32[128*64] 32768B, XOR-swizzled rows (conv2)
                           //   alias: sorted keys u32[16][256] 16384B (selection)
#define OFF_Z1    0        //   alias: f32[64]  (post-conv2)
#define OFF_Z2    256      //   alias: f32[128]
#define OFF_Z3    768      //   alias: f32[64]
#define OFF_Z4    1024     //   alias: f32[4]
#define OFF_H1S   32768    // f32[64*32] 8192B (conv phases)
#define OFF_SKEY  32768    //   alias: u32[256] 1024B (merge, pre-conv1)
#define OFF_W1S   40960    // f32[320] 1280B
#define OFF_B1S   42240    // f32[64]  256B
#define OFF_B2S   42496    // f32[128] 512B
#define OFF_XK    43008    // f32[160] 640B  (alias: featsh[0..127] post-conv1)
#define OFF_MASK  43648    // f32[32]  128B
#define OFF_SEL   43776    // u32[32]  128B
#define OFF_TAIL  43904    // f32[4]   16B   (rel.x, rel.y, v2, v3)
#define SMEM_TOTAL 43920

#define KEY_BIAS 0x3C000000u

__global__ __launch_bounds__(TPB, 5)
void controller_kernel(
    const float4* __restrict__ states4,   // [N,4]
    const float*  __restrict__ goals,     // [N,2]
    const float*  __restrict__ W1,  const float* __restrict__ b1,
    const float*  __restrict__ W2,  const float* __restrict__ b2,
    const float*  __restrict__ Wd1, const float* __restrict__ bd1,
    const float*  __restrict__ Wd2, const float* __restrict__ bd2,
    const float*  __restrict__ Wd3, const float* __restrict__ bd3,
    const float*  __restrict__ Wd4, const float* __restrict__ bd4,
    float* __restrict__ out)              // [N,2]
{
    __shared__ __align__(16) char smem[SMEM_TOTAL];
    float4*             w2s4    = (float4*)(smem + OFF_W2S);
    unsigned*           sortbuf = (unsigned*)(smem + OFF_W2S);    // alias (selection)
    float*              h1s     = (float*)(smem + OFF_H1S);
    unsigned*           skey32  = (unsigned*)(smem + OFF_SKEY);
    float*              W1s     = (float*)(smem + OFF_W1S);
    float*              b1s     = (float*)(smem + OFF_B1S);
    float*              b2s     = (float*)(smem + OFF_B2S);
    float*              xkflat  = (float*)(smem + OFF_XK);
    float*              featsh  = (float*)(smem + OFF_XK);        // alias (post-conv1)
    float*              masksh  = (float*)(smem + OFF_MASK);
    unsigned*           selsh   = (unsigned*)(smem + OFF_SEL);
    float*              tailf   = (float*)(smem + OFF_TAIL);
    float*              z1s     = (float*)(smem + OFF_Z1);
    float*              z2s     = (float*)(smem + OFF_Z2);
    float*              z3s     = (float*)(smem + OFF_Z3);
    float*              z4s     = (float*)(smem + OFF_Z4);

    const int tid  = threadIdx.x;
    const int i    = blockIdx.x;
    const int lane = tid & 31;
    const int wid  = tid >> 5;

    const float4 si = states4[i];

    // ---- early staging of small weights (overlaps phase A latency) ----
    for (int t = tid; t < 320; t += TPB) W1s[t] = W1[t];
    if (tid < 64)  b1s[tid] = b1[tid];
    if (tid < 128) b2s[tid] = b2[tid];

    // ---- phase A: planar distances -> exact u32 keys (monotone in (d, k)) ----
    unsigned key[JPT];
    {
        const float2* stxy = (const float2*)states4;
        #pragma unroll
        for (int k = 0; k < JPT; k++) {
            int j = tid + (k << 8);
            float2 sj = stxy[2 * j];
            float dx = si.x - sj.x;
            float dy = si.y - sj.y;
            float d  = sqrtf(dx * dx + dy * dy + 1e-4f);   // identical to ref path
            key[k] = ((__float_as_uint(d) - KEY_BIAS) << 4) | (unsigned)k;
        }
    }

    // ---- per-thread Batcher odd-even mergesort of 16 keys (registers, 63 CEs) ----
    #pragma unroll
    for (int p = 1; p < 16; p <<= 1) {
        #pragma unroll
        for (int q = p; q > 0; q >>= 1) {
            #pragma unroll
            for (int jj = (q & (p - 1)); jj + q < 16; jj += (q << 1)) {
                #pragma unroll
                for (int ii = 0; ii < q; ii++) {
                    if (ii + jj + q < 16 &&
                        ((ii + jj) / (p << 1) == (ii + jj + q) / (p << 1))) {
                        unsigned a = key[ii + jj], b = key[ii + jj + q];
                        key[ii + jj]     = umin(a, b);
                        key[ii + jj + q] = umax(a, b);
                    }
                }
            }
        }
    }
    // spill sorted column to smem (own column only -> warp-sync safe, no barrier)
    #pragma unroll
    for (int k = 0; k < 16; k++) sortbuf[(k << 8) + tid] = key[k];

    // ---- stage 1: per-warp exact top-32, REDUX tournament ----
    unsigned winkey = 0;
    int      winlane = 0;
    {
        unsigned cur = key[0];
        int head = 1;
        #pragma unroll
        for (int r = 0; r < TOPK; r++) {
            unsigned g = __reduce_min_sync(0xffffffffu, cur);
            unsigned mm = __ballot_sync(0xffffffffu, cur == g);
            int l = __ffs(mm) - 1;          // lowest lane = lowest j on key ties
            if (lane == r) { winkey = g; winlane = l; }
            if (lane == l) {                // winner pops next from its sorted list
                cur = (head < 16) ? sortbuf[(head << 8) + tid] : 0xffffffffu;
                head++;
            }
        }
    }
    // publish rank-`lane` winner: u32 key to smem, its j kept in a register
    const unsigned myj = (unsigned)((wid << 5) + winlane) + ((winkey & 15u) << 8);
    skey32[tid] = winkey;
    __syncthreads();

    // ---- merge phase: stage W2 (overlaps LDS chains) + rank-merge ----
    {
        const float4* W2v = (const float4*)W2;     // [128][16] float4
        #pragma unroll
        for (int t = tid; t < 2048; t += TPB) {
            int o = t >> 4, cb = t & 15;
            // XOR swizzle keyed on o>>1 (conv2 reads o-pairs): conflict-free, 0B pad
            w2s4[(o << 4) + (cb ^ ((o >> 1) & 7))] = W2v[t];
        }
    }
    {
        // stable rank-merge on u32 keys: for equal keys, lower warp = lower j wins,
        // implemented exactly via <= against lower-indexed warps, < against higher.
        const unsigned mykey = winkey;
        int rank = lane;                           // position in own sorted list
        #pragma unroll
        for (int ww = 0; ww < 8; ww++) {
            if (ww == wid) continue;
            const unsigned* arr = skey32 + (ww << 5);
            const bool low = (ww < wid);
            int pos = 0;
            #pragma unroll
            for (int s = 16; s; s >>= 1) {
                unsigned v = arr[pos + s - 1];
                bool adv = low ? (v <= mykey) : (v < mykey);
                pos += adv ? s : 0;
            }
            rank += pos;
        }
        if (rank < TOPK) selsh[rank] = myj;
    }
    __syncthreads();

    // ---- gather xk rows + obs mask + tail features ----
    if (tid < TOPK) {
        int j = (int)selsh[tid];
        float4 sj = states4[j];
        float dx = si.x - sj.x;
        float dy = si.y - sj.y;
        xkflat[tid * 5 + 0] = dx;
        xkflat[tid * 5 + 1] = dy;
        xkflat[tid * 5 + 2] = si.z - sj.z;
        xkflat[tid * 5 + 3] = si.w - sj.w;
        xkflat[tid * 5 + 4] = (j == i) ? 1.0f : 0.0f;
        masksh[tid] = (sqrtf(dx * dx + dy * dy) < 1.0f) ? 1.0f : 0.0f;
    }
    if (tid == 0) {
        float gx = goals[2 * i], gy = goals[2 * i + 1];
        tailf[0] = si.x - gx;
        tailf[1] = si.y - gy;
        tailf[2] = si.z;
        tailf[3] = si.w;
    }
    __syncthreads();

    // ---- conv1 5->64, float4-vectorized (h[c][p] = xkflat[c*32+p]) ----
    {
        const float4* xk4 = (const float4*)xkflat;
        float4*       h4  = (float4*)h1s;
        #pragma unroll
        for (int u = 0; u < 2; u++) {
            int idx = tid + (u << 8);        // 0..511 float4-units
            int o = idx >> 3, p4 = idx & 7;
            float bb = b1s[o];
            float4 a = make_float4(bb, bb, bb, bb);
            #pragma unroll
            for (int c = 0; c < 5; c++) {    // c ascending: bit-identical chain
                float w = W1s[o * 5 + c];
                float4 x = xk4[(c << 3) + p4];
                a.x = fmaf(w, x.x, a.x); a.y = fmaf(w, x.y, a.y);
                a.z = fmaf(w, x.z, a.z); a.w = fmaf(w, x.w, a.w);
            }
            a.x = fmaxf(a.x, 0.0f); a.y = fmaxf(a.y, 0.0f);
            a.z = fmaxf(a.z, 0.0f); a.w = fmaxf(a.w, 0.0f);
            h4[idx] = a;
        }
    }
    __syncthreads();

    // ---- conv2 64->128 + masked argmax: (2o x 8p) tile, f32x2 p-pairs ----
    {
        const int og = tid >> 2;           // o-pair group: o = 2*og, 2*og+1 (0..63)
        const int pg = tid & 3;            // p base = 8*pg
        const int sw = og & 7;             // XOR-swizzle key (matches store: o>>1)
        unsigned long long accp[2][4];     // [oo][p-pair], f32x2 accumulators
        #pragma unroll
        for (int q = 0; q < 4; q++) { accp[0][q] = 0ull; accp[1][q] = 0ull; }

        #pragma unroll 2
        for (int cb = 0; cb < 16; cb++) {
            const float4 wv0 = w2s4[(((og << 1) + 0) << 4) + (cb ^ sw)];
            const float4 wv1 = w2s4[(((og << 1) + 1) << 4) + (cb ^ sw)];
            #pragma unroll
            for (int cc = 0; cc < 4; cc++) {       // c ascending: bit-identical order
                const int c = (cb << 2) + cc;
                const ulonglong2 ha = *reinterpret_cast<const ulonglong2*>(
                    &h1s[(c << 5) + (pg << 3)]);
                const ulonglong2 hb = *reinterpret_cast<const ulonglong2*>(
                    &h1s[(c << 5) + (pg << 3) + 4]);
                float w0 = (cc == 0) ? wv0.x : (cc == 1) ? wv0.y : (cc == 2) ? wv0.z : wv0.w;
                float w1 = (cc == 0) ? wv1.x : (cc == 1) ? wv1.y : (cc == 2) ? wv1.z : wv1.w;
                unsigned long long wd0, wd1;
                asm("mov.b64 %0, {%1, %1};" : "=l"(wd0) : "f"(w0));
                asm("mov.b64 %0, {%1, %1};" : "=l"(wd1) : "f"(w1));
                asm("fma.rn.f32x2 %0, %1, %2, %0;" : "+l"(accp[0][0]) : "l"(wd0), "l"(ha.x));
                asm("fma.rn.f32x2 %0, %1, %2, %0;" : "+l"(accp[0][1]) : "l"(wd0), "l"(ha.y));
                asm("fma.rn.f32x2 %0, %1, %2, %0;" : "+l"(accp[0][2]) : "l"(wd0), "l"(hb.x));
                asm("fma.rn.f32x2 %0, %1, %2, %0;" : "+l"(accp[0][3]) : "l"(wd0), "l"(hb.y));
                asm("fma.rn.f32x2 %0, %1, %2, %0;" : "+l"(accp[1][0]) : "l"(wd1), "l"(ha.x));
                asm("fma.rn.f32x2 %0, %1, %2, %0;" : "+l"(accp[1][1]) : "l"(wd1), "l"(ha.y));
                asm("fma.rn.f32x2 %0, %1, %2, %0;" : "+l"(accp[1][2]) : "l"(wd1), "l"(hb.x));
                asm("fma.rn.f32x2 %0, %1, %2, %0;" : "+l"(accp[1][3]) : "l"(wd1), "l"(hb.y));
            }
        }

        float mk[8];
        {
            float4 m0 = ((const float4*)masksh)[(pg << 1)];
            float4 m1 = ((const float4*)masksh)[(pg << 1) + 1];
            mk[0] = m0.x; mk[1] = m0.y; mk[2] = m0.z; mk[3] = m0.w;
            mk[4] = m1.x; mk[5] = m1.y; mk[6] = m1.z; mk[7] = m1.w;
        }

        #pragma unroll
        for (int oo = 0; oo < 2; oo++) {
            int o = (og << 1) + oo;
            float bb = b2s[o];
            float acc[8];
            #pragma unroll
            for (int q = 0; q < 4; q++)
                asm("mov.b64 {%0, %1}, %2;"
                    : "=f"(acc[2 * q]), "=f"(acc[2 * q + 1]) : "l"(accp[oo][q]));
            float bv = 0.0f;
            int   bp = 0;
            #pragma unroll
            for (int pp = 0; pp < 8; pp++) {
                float v = fmaxf(acc[pp] + bb, 0.0f) * mk[pp];
                if (pp == 0) { bv = v; bp = (pg << 3); }
                else if (v > bv) { bv = v; bp = (pg << 3) + pp; }  // strict >: first index
            }
            // combine across the 4 threads (quad) sharing this o
            #pragma unroll
            for (int off = 1; off < 4; off <<= 1) {
                float ov = __shfl_xor_sync(0xffffffffu, bv, off);
                int   op = __shfl_xor_sync(0xffffffffu, bp, off);
                if (ov > bv || (ov == bv && op < bp)) { bv = ov; bp = op; }
            }
            if (pg == 0) featsh[o] = (float)bp;
        }
    }
    __syncthreads();

    // ---- MLP 132 -> 64 -> 128 -> 64 -> 4 (half-warp float4 dots) ----
    const int hw = lane >> 4;        // half-warp id (0/1)
    const int hl = lane & 15;        // lane within half

    // z1: 64 outputs, 2 per warp per iter
    #pragma unroll
    for (int it = 0; it < 4; it++) {
        int o = (wid << 3) + (it << 1) + hw;
        const float4* wr = (const float4*)(Wd1 + o * 132);
        float4 wa = wr[hl];
        float4 fa = *(const float4*)&featsh[hl << 2];
        float s = wa.x * fa.x;
        s = fmaf(wa.y, fa.y, s); s = fmaf(wa.z, fa.z, s); s = fmaf(wa.w, fa.w, s);
        float4 wb = wr[hl + 16];
        float4 fb = *(const float4*)&featsh[64 + (hl << 2)];
        s = fmaf(wb.x, fb.x, s); s = fmaf(wb.y, fb.y, s);
        s = fmaf(wb.z, fb.z, s); s = fmaf(wb.w, fb.w, s);
        if (hl == 0) {
            float4 wc = wr[32];
            float4 fc = *(const float4*)tailf;
            s = fmaf(wc.x, fc.x, s); s = fmaf(wc.y, fc.y, s);
            s = fmaf(wc.z, fc.z, s); s = fmaf(wc.w, fc.w, s);
        }
        #pragma unroll
        for (int off = 8; off; off >>= 1) s += __shfl_xor_sync(0xffffffffu, s, off);
        if (hl == 0) z1s[o] = fmaxf(s + bd1[o], 0.0f);
    }
    __syncthreads();

    // z2: 128 outputs, 2 per warp per iter
    #pragma unroll
    for (int it = 0; it < 8; it++) {
        int o = (wid << 4) + (it << 1) + hw;
        float4 w = ((const float4*)(Wd2 + (o << 6)))[hl];
        float4 z = ((const float4*)z1s)[hl];
        float s = w.x * z.x;
        s = fmaf(w.y, z.y, s); s = fmaf(w.z, z.z, s); s = fmaf(w.w, z.w, s);
        #pragma unroll
        for (int off = 8; off; off >>= 1) s += __shfl_xor_sync(0xffffffffu, s, off);
        if (hl == 0) z2s[o] = fmaxf(s + bd2[o], 0.0f);
    }
    __syncthreads();

    // z3: 64 outputs, 2 per warp per iter (128 inputs = two float4 passes)
    #pragma unroll
    for (int it = 0; it < 4; it++) {
        int o = (wid << 3) + (it << 1) + hw;
        const float4* wr = (const float4*)(Wd3 + (o << 7));
        float4 wa = wr[hl];
        float4 za = ((const float4*)z2s)[hl];
        float s = wa.x * za.x;
        s = fmaf(wa.y, za.y, s); s = fmaf(wa.z, za.z, s); s = fmaf(wa.w, za.w, s);
        float4 wb = wr[hl + 16];
        float4 zb = ((const float4*)z2s)[hl + 16];
        s = fmaf(wb.x, zb.x, s); s = fmaf(wb.y, zb.y, s);
        s = fmaf(wb.z, zb.z, s); s = fmaf(wb.w, zb.w, s);
        #pragma unroll
        for (int off = 8; off; off >>= 1) s += __shfl_xor_sync(0xffffffffu, s, off);
        if (hl == 0) z3s[o] = fmaxf(s + bd3[o], 0.0f);
    }
    __syncthreads();

    // z4: 4 outputs on warps 0-1
    if (wid < 2) {
        int o = (wid << 1) + hw;
        float4 w = ((const float4*)(Wd4 + (o << 6)))[hl];
        float4 z = ((const float4*)z3s)[hl];
        float s = w.x * z.x;
        s = fmaf(w.y, z.y, s); s = fmaf(w.z, z.z, s); s = fmaf(w.w, z.w, s);
        #pragma unroll
        for (int off = 8; off; off >>= 1) s += __shfl_xor_sync(0xffffffffu, s, off);
        if (hl == 0) z4s[o] = s + bd4[o];
    }
    __syncthreads();

    // ---- gains + control output ----
    if (tid == 0) {
        float k0 = 2.0f / (1.0f + expf(-z4s[0])) + 0.2f;
        float k1 = 2.0f / (1.0f + expf(-z4s[1])) + 0.2f;
        float k2 = 2.0f / (1.0f + expf(-z4s[2])) + 0.2f;
        float k3 = 2.0f / (1.0f + expf(-z4s[3])) + 0.2f;
        float rx = tailf[0], ry = tailf[1];
        float v2 = tailf[2], v3 = tailf[3];
        out[2 * i + 0] = -(k0 * rx + k1 * v2);
        out[2 * i + 1] = -(k2 * ry + k3 * v3);
    }
}

extern "C" void kernel_launch(void* const* d_in, const int* in_sizes, int n_in,
                              void* d_out, int out_size)
{
    (void)in_sizes; (void)n_in; (void)out_size;
    controller_kernel<<<N_AGENTS, TPB>>>(
        (const float4*)d_in[0],  (const float*)d_in[1],
        (const float*)d_in[2],   (const float*)d_in[3],
        (const float*)d_in[4],   (const float*)d_in[5],
        (const float*)d_in[6],   (const float*)d_in[7],
        (const float*)d_in[8],   (const float*)d_in[9],
        (const float*)d_in[10],  (const float*)d_in[11],
        (const float*)d_in[12],  (const float*)d_in[13],
        (float*)d_out);
}